// round 9
// baseline (speedup 1.0000x reference)
#include <cuda_runtime.h>

#define Bz 4
#define C_IN 32
#define NPIX 4096                        // 64*64 pooled pixels
#define NODES_PER_B (NPIX * C_IN)        // 131072
#define NODES_TOTAL (Bz * NODES_PER_B)   // 524288
#define ADJ_PER_B   ((long)NPIX * NPIX)  // 16777216 floats
#define EPSV 1e-6f

// patch certainty for pooled pixel p of batch b (x_var is 1MB, L2-resident)
__device__ __forceinline__ float certainty(const float4* __restrict__ xv4, int b, int p)
{
    int R = p >> 6, C = p & 63;
    float s = 0.f;
    #pragma unroll
    for (int i = 0; i < 4; ++i) {
        float4 v = __ldg(&xv4[((b * 256 + (R * 4 + i)) << 6) + C]);
        s += v.x + v.y + v.z + v.w;
    }
    return 1.f - s * (1.f / 16.f);
}

// 128 blocks x 512 threads; block owns 2 pooled rows (one batch).
// Deep-MLP pooling (32 independent coalesced float4 loads per thread),
// 2-stage smem reduction, tiled nodes write, sparse edge patches.
__global__ __launch_bounds__(512) void patch_all(
    const float* __restrict__ x_feat,
    const float* __restrict__ x_var,
    float* __restrict__ out)
{
    __shared__ float red[2][4][64];      // [half][quad][Cc] channel-partials
    __shared__ float sums[2][64];        // final pooled sums * 1/16

    int blk = blockIdx.x;                // 0..127
    int b   = blk >> 5;                  // batch (32 blocks per batch)
    int R0  = (blk & 31) << 1;           // first of 2 pooled rows

    int tid  = threadIdx.x;              // 0..511
    int half = tid >> 8;                 // which pooled row
    int quad = (tid >> 6) & 3;           // which image row within 4x4 patch
    int Cc   = tid & 63;                 // pooled column

    // ---- pooling: 32 independent coalesced loads (one per channel) ----
    {
        const float4* xf4 = (const float4*)x_feat;
        int rowbase = ((R0 + half) * 4 + quad) << 6;   // image row offset (in float4)
        float acc = 0.f;
        #pragma unroll
        for (int c = 0; c < C_IN; ++c) {
            // lanes 0..31 read 32 consecutive float4 => 512B contiguous
            float4 v = __ldg(&xf4[(((b * C_IN + c) << 8) << 6) + (rowbase << 0) + (c * 0) + Cc
                                  + ((long)0)]);
            // NOTE: index spelled out below for clarity instead:
            (void)v;
            float4 w = __ldg(&xf4[((((b * C_IN + c) << 8) + ((R0 + half) * 4 + quad)) << 6) + Cc]);
            acc += w.x + w.y + w.z + w.w;
        }
        red[half][quad][Cc] = acc;
    }
    __syncthreads();

    // ---- reduce 4 quads -> pooled sum (threads 0..127) ----
    if (tid < 128) {
        int h = tid >> 6, C = tid & 63;
        sums[h][C] = (red[h][0][C] + red[h][1][C] + red[h][2][C] + red[h][3][C])
                     * (1.f / 16.f);
    }
    __syncthreads();

    // ---- nodes: 2 rows x 64 pix x 32 copies = 4096 stores, 8 per thread ----
    {
        float* nodesb = out + (long)b * NODES_PER_B;
        #pragma unroll
        for (int k = 0; k < 8; ++k) {
            int sidx = tid + (k << 9);          // 0..4095
            int j    = sidx >> 7;               // copy 0..31
            int rem  = sidx & 127;
            int h    = rem >> 6;
            int C    = rem & 63;
            nodesb[j * NPIX + (R0 + h) * 64 + C] = sums[h][C];
        }
    }

    // ---- edges: 2 rows x 64 pix x 4 dirs = 512 tasks, 1 per thread ----
    {
        int pix = tid >> 2;                     // 0..127
        int sel = tid & 3;
        int h   = pix >> 6;
        int co  = pix & 63;
        int R   = R0 + h;
        int t   = R * 64 + co;
        int f; bool valid;
        if      (sel == 0) { f = t - 64; valid = (R > 0);   }
        else if (sel == 1) { f = t + 64; valid = (R < 63);  }
        else if (sel == 2) { f = t - 1;  valid = (co > 0);  }
        else               { f = t + 1;  valid = (co < 63); }
        if (valid) {
            const float4* xv4 = (const float4*)x_var;
            float w = certainty(xv4, b, f) - certainty(xv4, b, t);
            if (w > EPSV)
                out[NODES_TOTAL + (long)b * ADJ_PER_B + (long)f * NPIX + t] = w;
        }
    }
}

extern "C" void kernel_launch(void* const* d_in, const int* in_sizes, int n_in,
                              void* d_out, int out_size)
{
    const float* x_feat = (const float*)d_in[0];
    const float* x_var  = (const float*)d_in[1];
    float* out = (float*)d_out;

    // Driver fill path (~6.4 TB/s): zero the 256MB adj region.
    cudaMemsetAsync(out + NODES_TOTAL, 0, (long)Bz * ADJ_PER_B * sizeof(float));

    // Nodes + sparse edges; single wave, deep MLP.
    patch_all<<<128, 512>>>(x_feat, x_var, out);
}